// round 15
// baseline (speedup 1.0000x reference)
#include <cuda_runtime.h>
#include <cstdint>

// Problem sizes
#define NB   128
#define NT   256
#define Bb   16
#define Tt   2000
#define Cc   128
#define Gg   512
#define Hh   512
#define Vv   256

// Group decomposition: 4 independent groups x 32 blocks; each group owns 4 batches.
#define NG   4
#define GB   32                     // blocks per group
#define BPG  4                      // batches per group

#define NBAR 6001ULL                // barriers per launch per group: 1 init + 3*Tt
#define LAUNCH_ARR (NBAR * (unsigned long long)GB)

// ---------------- global scratch (no allocations allowed) ----------------
__device__ __align__(16) float g_h[2][Bb * Gg];    // double-buffered hidden state
__device__ __align__(16) float g_hid[Bb * Hh];
__device__ __align__(16) float g_val[Bb * Vv];     // logits + gumbel (for argmax)

// per-group monotonic arrival counters, each alone on a 512B-strided line.
__device__ __align__(1024) unsigned long long g_cnt[NG * 64];   // use [g*64]

struct __align__(16) Smem {
    float sh[BPG * Gg];    // 8KB: h staged (pre-loop + each P2); persists into P1
    float shid[BPG * Hh];  // 8KB: hid staged in P3
    float sx[BPG * Cc];    // 2KB: x = cond_t + embedding[prev]
    int   sprev[BPG];
    unsigned long long base0;
};

// ---------------- threefry2x32 (exact JAX semantics) ----------------
__device__ __forceinline__ unsigned rotl32(unsigned x, int r) {
    return (x << r) | (x >> (32 - r));
}

__device__ __forceinline__ void tf2x32(unsigned k0, unsigned k1,
                                       unsigned x0, unsigned x1,
                                       unsigned& o0, unsigned& o1) {
    unsigned ks2 = k0 ^ k1 ^ 0x1BD11BDAu;
    x0 += k0; x1 += k1;
    x0 += x1; x1 = rotl32(x1, 13); x1 ^= x0;
    x0 += x1; x1 = rotl32(x1, 15); x1 ^= x0;
    x0 += x1; x1 = rotl32(x1, 26); x1 ^= x0;
    x0 += x1; x1 = rotl32(x1, 6);  x1 ^= x0;
    x0 += k1; x1 += ks2 + 1u;
    x0 += x1; x1 = rotl32(x1, 17); x1 ^= x0;
    x0 += x1; x1 = rotl32(x1, 29); x1 ^= x0;
    x0 += x1; x1 = rotl32(x1, 16); x1 ^= x0;
    x0 += x1; x1 = rotl32(x1, 24); x1 ^= x0;
    x0 += ks2; x1 += k0 + 2u;
    x0 += x1; x1 = rotl32(x1, 13); x1 ^= x0;
    x0 += x1; x1 = rotl32(x1, 15); x1 ^= x0;
    x0 += x1; x1 = rotl32(x1, 26); x1 ^= x0;
    x0 += x1; x1 = rotl32(x1, 6);  x1 ^= x0;
    x0 += k0; x1 += k1 + 3u;
    x0 += x1; x1 = rotl32(x1, 17); x1 ^= x0;
    x0 += x1; x1 = rotl32(x1, 29); x1 ^= x0;
    x0 += x1; x1 = rotl32(x1, 16); x1 ^= x0;
    x0 += x1; x1 = rotl32(x1, 24); x1 ^= x0;
    x0 += k1; x1 += ks2 + 4u;
    x0 += x1; x1 = rotl32(x1, 13); x1 ^= x0;
    x0 += x1; x1 = rotl32(x1, 15); x1 ^= x0;
    x0 += x1; x1 = rotl32(x1, 26); x1 ^= x0;
    x0 += x1; x1 = rotl32(x1, 6);  x1 ^= x0;
    x0 += ks2; x1 += k0 + 5u;
    o0 = x0; o1 = x1;
}

__device__ __forceinline__ float sigmoidf_(float x) {
    return 1.0f / (1.0f + expf(-x));
}

// ---------------- per-group barrier: acq_rel RMW arrival + acquire-poll ----------
__device__ __forceinline__ unsigned long long cnt_acquire(const unsigned long long* p) {
    unsigned long long v;
    asm volatile("ld.acquire.gpu.global.u64 %0, [%1];" : "=l"(v) : "l"(p));
    return v;
}

// bar.sync before the RMW orders all block threads' writes before the release
// half; the acquire half / acquire-poll synchronizes with the whole RMW chain
// -> all 32 blocks' writes visible after the barrier. Last arriver skips poll.
__device__ __forceinline__ void group_barrier(unsigned long long* cnt,
                                              unsigned long long thresh) {
    __syncthreads();
    if (threadIdx.x == 0) {
        unsigned long long c;
        asm volatile("atom.acq_rel.gpu.global.add.u64 %0, [%1], %2;"
                     : "=l"(c) : "l"(cnt), "l"(1ULL) : "memory");
        if (c != thresh - 1ULL) {
            while (cnt_acquire(cnt) < thresh) { }
        }
    }
    __syncthreads();
}

// warp-cooperative argmax over g_val[b][0..255], first-index tie-break (jnp.argmax)
__device__ __forceinline__ int warp_argmax_b(int b, int lane) {
    float bestv = -1e30f; int besti = 0;
#pragma unroll
    for (int k = 0; k < 8; ++k) {
        int v = lane + 32 * k;
        float x = __ldcg(&g_val[b * Vv + v]);
        if (x > bestv) { bestv = x; besti = v; }
    }
#pragma unroll
    for (int off = 16; off; off >>= 1) {
        float ov = __shfl_xor_sync(0xffffffffu, bestv, off);
        int   oi = __shfl_xor_sync(0xffffffffu, besti, off);
        if (ov > bestv || (ov == bestv && oi < besti)) { bestv = ov; besti = oi; }
    }
    return besti;
}

// runtime select from a [2][4] register array
__device__ __forceinline__ float sel24(const float a[2][4], int uu, int b) {
    float x0 = (b == 0) ? a[0][0] : (b == 1) ? a[0][1] : (b == 2) ? a[0][2] : a[0][3];
    float x1 = (b == 0) ? a[1][0] : (b == 1) ? a[1][1] : (b == 2) ? a[1][2] : a[1][3];
    return (uu == 0) ? x0 : x1;
}

__global__ void __launch_bounds__(NT, 1)
wavernn_persistent(const float* __restrict__ cond,
                   const float* __restrict__ h0,
                   const float* __restrict__ W_ih,
                   const float* __restrict__ W_hh,
                   const float* __restrict__ b_ih,
                   const float* __restrict__ b_hh,
                   const float* __restrict__ W_hid,
                   const float* __restrict__ b_hid,
                   const float* __restrict__ W_out,
                   const float* __restrict__ b_out,
                   const float* __restrict__ emb,
                   float* __restrict__ out) {
    __shared__ Smem sm;
    const int tid  = threadIdx.x;
    const int g    = blockIdx.x >> 5;        // group id 0..3
    const int gbid = blockIdx.x & 31;        // block id within group
    const int wid  = tid >> 5;               // 8 warps
    const int lane = tid & 31;
    const int bg0  = g * BPG;                // first global batch of this group
    unsigned long long* cnt = &g_cnt[g * 64];

    if (tid == 0) {
        unsigned long long c0 = cnt_acquire(cnt);
        sm.base0 = (c0 / LAUNCH_ARR) * LAUNCH_ARR;
    }
    __syncthreads();
    const unsigned long long base = sm.base0;
    unsigned long long bar = 0;

    float* out_logits  = out;                                // [B][T][V]
    float* out_samples = out + (size_t)Bb * Tt * Vv;         // [B][T]
    float* out_hfinal  = out + (size_t)Bb * Tt * Vv + (size_t)Bb * Tt; // [B][G]

    // ---- init: h[0] = h0 for this group's batches ----
    for (int i = gbid * NT + tid; i < BPG * Gg; i += GB * NT)
        __stcg(&g_h[0][bg0 * Gg + i], h0[bg0 * Gg + i]);
    group_barrier(cnt, base + (++bar) * GB);

    // pre-stage h(0) into smem (persists across the loop; refreshed in each P2)
    {
        const float4* src = (const float4*)(g_h[0] + bg0 * Gg);
        float4* dst = (float4*)sm.sh;
        for (int i = tid; i < (BPG * Gg) / 4; i += NT) dst[i] = __ldcg(src + i);
    }
    __syncthreads();

    for (int t = 0; t < Tt; ++t) {
        const int pb = t & 1;           // g_h[pb] = current h, g_h[pb^1] = h_new

        // ===== P1 prologue: prev (argmax of last step) + stage x =====
        // (h(t-1) already resident in sm.sh from last step's P2 staging)
        if (t == 0) {
            if (tid < BPG) sm.sprev[tid] = Vv / 2;   // mid-bucket
        } else if (wid < BPG) {
            int b = bg0 + wid;
            int besti = warp_argmax_b(b, lane);
            if (lane == 0) {
                sm.sprev[wid] = besti;
                if (gbid == 0) out_samples[b * Tt + (t - 1)] = (float)besti;
            }
        }
        __syncthreads();

        for (int i = tid; i < BPG * Cc; i += NT) {
            int lb = i >> 7, c = i & (Cc - 1);
            sm.sx[i] = __ldg(&cond[((size_t)(bg0 + lb) * Tt + t) * Cc + c]) +
                       __ldg(&emb[(size_t)sm.sprev[lb] * Cc + c]);
        }
        __syncthreads();

        // ===== P1: fused GRU gates + h update (16 units/block, warp = 2 units x 4 batches) =====
        {
            const int ub = gbid * 16 + wid * 2;   // first of this warp's 2 units
            float sr[2][4], sz[2][4], si[2][4], shn[2][4];
#pragma unroll
            for (int uu = 0; uu < 2; ++uu)
#pragma unroll
                for (int b = 0; b < 4; ++b) {
                    sr[uu][b] = 0.f; sz[uu][b] = 0.f; si[uu][b] = 0.f; shn[uu][b] = 0.f;
                }

            // x part: W_ih rows (u, G+u, 2G+u), row = 32 float4
            {
                float4 wr[2], wz[2], wn[2];
#pragma unroll
                for (int uu = 0; uu < 2; ++uu) {
                    int u = ub + uu;
                    wr[uu] = __ldg((const float4*)(W_ih + (size_t)u * Cc) + lane);
                    wz[uu] = __ldg((const float4*)(W_ih + (size_t)(Gg + u) * Cc) + lane);
                    wn[uu] = __ldg((const float4*)(W_ih + (size_t)(2 * Gg + u) * Cc) + lane);
                }
#pragma unroll
                for (int b = 0; b < 4; ++b) {
                    float4 x4 = ((const float4*)(sm.sx + b * Cc))[lane];
#pragma unroll
                    for (int uu = 0; uu < 2; ++uu) {
                        sr[uu][b] = fmaf(wr[uu].x, x4.x, fmaf(wr[uu].y, x4.y, fmaf(wr[uu].z, x4.z, fmaf(wr[uu].w, x4.w, sr[uu][b]))));
                        sz[uu][b] = fmaf(wz[uu].x, x4.x, fmaf(wz[uu].y, x4.y, fmaf(wz[uu].z, x4.z, fmaf(wz[uu].w, x4.w, sz[uu][b]))));
                        si[uu][b] = fmaf(wn[uu].x, x4.x, fmaf(wn[uu].y, x4.y, fmaf(wn[uu].z, x4.z, fmaf(wn[uu].w, x4.w, si[uu][b]))));
                    }
                }
            }
            // h part: W_hh rows (u, G+u, 2G+u), row = 128 float4
#pragma unroll
            for (int k = 0; k < 4; ++k) {
                int c4 = lane + 32 * k;
                float4 wr[2], wz[2], wn[2];
#pragma unroll
                for (int uu = 0; uu < 2; ++uu) {
                    int u = ub + uu;
                    wr[uu] = __ldg((const float4*)(W_hh + (size_t)u * Gg) + c4);
                    wz[uu] = __ldg((const float4*)(W_hh + (size_t)(Gg + u) * Gg) + c4);
                    wn[uu] = __ldg((const float4*)(W_hh + (size_t)(2 * Gg + u) * Gg) + c4);
                }
#pragma unroll
                for (int b = 0; b < 4; ++b) {
                    float4 h4 = ((const float4*)(sm.sh + b * Gg))[c4];
#pragma unroll
                    for (int uu = 0; uu < 2; ++uu) {
                        sr[uu][b]  = fmaf(wr[uu].x, h4.x, fmaf(wr[uu].y, h4.y, fmaf(wr[uu].z, h4.z, fmaf(wr[uu].w, h4.w, sr[uu][b]))));
                        sz[uu][b]  = fmaf(wz[uu].x, h4.x, fmaf(wz[uu].y, h4.y, fmaf(wz[uu].z, h4.z, fmaf(wz[uu].w, h4.w, sz[uu][b]))));
                        shn[uu][b] = fmaf(wn[uu].x, h4.x, fmaf(wn[uu].y, h4.y, fmaf(wn[uu].z, h4.z, fmaf(wn[uu].w, h4.w, shn[uu][b]))));
                    }
                }
            }
            // butterfly reduce (same per-accumulator order -> bit-identical)
#pragma unroll
            for (int off = 16; off; off >>= 1) {
#pragma unroll
                for (int uu = 0; uu < 2; ++uu)
#pragma unroll
                    for (int b = 0; b < 4; ++b) {
                        sr[uu][b]  += __shfl_xor_sync(0xffffffffu, sr[uu][b],  off);
                        sz[uu][b]  += __shfl_xor_sync(0xffffffffu, sz[uu][b],  off);
                        si[uu][b]  += __shfl_xor_sync(0xffffffffu, si[uu][b],  off);
                        shn[uu][b] += __shfl_xor_sync(0xffffffffu, shn[uu][b], off);
                    }
            }
            if (lane < 8) {
                int uu = lane >> 2, b = lane & 3;
                int u  = ub + uu;
                float vr  = sel24(sr,  uu, b);
                float vz  = sel24(sz,  uu, b);
                float vi  = sel24(si,  uu, b);
                float vhn = sel24(shn, uu, b);
                float r = sigmoidf_(vr + __ldg(&b_ih[u])      + __ldg(&b_hh[u]));
                float z = sigmoidf_(vz + __ldg(&b_ih[Gg + u]) + __ldg(&b_hh[Gg + u]));
                float n = tanhf((vi + __ldg(&b_ih[2 * Gg + u])) +
                                r * (vhn + __ldg(&b_hh[2 * Gg + u])));
                float hold = sm.sh[b * Gg + u];
                __stcg(&g_h[pb ^ 1][(bg0 + b) * Gg + u], (1.0f - z) * n + z * hold);
            }
        }
        group_barrier(cnt, base + (++bar) * GB);

        // ===== P2: stage h_new (persists to next P1), hid = relu(h_new @ W_hid.T + b) =====
        {
            const float4* src = (const float4*)(g_h[pb ^ 1] + bg0 * Gg);
            float4* dst = (float4*)sm.sh;
            for (int i = tid; i < (BPG * Gg) / 4; i += NT) dst[i] = __ldcg(src + i);
        }
        __syncthreads();
        {
            const int ub = gbid * 16 + wid * 2;
            float acc[2][4];
#pragma unroll
            for (int uu = 0; uu < 2; ++uu)
#pragma unroll
                for (int b = 0; b < 4; ++b) acc[uu][b] = 0.f;
#pragma unroll
            for (int k = 0; k < 4; ++k) {
                int c4 = lane + 32 * k;
                float4 w[2];
#pragma unroll
                for (int uu = 0; uu < 2; ++uu)
                    w[uu] = __ldg((const float4*)(W_hid + (size_t)(ub + uu) * Gg) + c4);
#pragma unroll
                for (int b = 0; b < 4; ++b) {
                    float4 h4 = ((const float4*)(sm.sh + b * Gg))[c4];
#pragma unroll
                    for (int uu = 0; uu < 2; ++uu)
                        acc[uu][b] = fmaf(w[uu].x, h4.x, fmaf(w[uu].y, h4.y, fmaf(w[uu].z, h4.z, fmaf(w[uu].w, h4.w, acc[uu][b]))));
                }
            }
#pragma unroll
            for (int off = 16; off; off >>= 1)
#pragma unroll
                for (int uu = 0; uu < 2; ++uu)
#pragma unroll
                    for (int b = 0; b < 4; ++b)
                        acc[uu][b] += __shfl_xor_sync(0xffffffffu, acc[uu][b], off);
            if (lane < 8) {
                int uu = lane >> 2, b = lane & 3;
                int u  = ub + uu;
                float v = sel24(acc, uu, b);
                __stcg(&g_hid[(bg0 + b) * Hh + u], fmaxf(v + __ldg(&b_hid[u]), 0.0f));
            }
        }
        group_barrier(cnt, base + (++bar) * GB);

        // ===== P3: logits + gumbel + val (8 rows/block, warp = 1 row x 4 batches) =====
        {
            const float4* src = (const float4*)(g_hid + bg0 * Hh);
            float4* dst = (float4*)sm.shid;
            for (int i = tid; i < (BPG * Hh) / 4; i += NT) dst[i] = __ldcg(src + i);
        }
        __syncthreads();
        {
            // per-step JAX key: split(key(1), T)[t] = threefry((0,1),(0,t))
            unsigned kt0, kt1;
            tf2x32(0u, 1u, 0u, (unsigned)t, kt0, kt1);

            const int v = gbid * 8 + wid;     // 8 logit rows per block, warp = 1 row x 4 batches
            float acc[4];
#pragma unroll
            for (int b = 0; b < 4; ++b) acc[b] = 0.f;
#pragma unroll
            for (int k = 0; k < 4; ++k) {
                int c4 = lane + 32 * k;
                float4 w = __ldg((const float4*)(W_out + (size_t)v * Hh) + c4);
#pragma unroll
                for (int b = 0; b < 4; ++b) {
                    float4 h4 = ((const float4*)(sm.shid + b * Hh))[c4];
                    acc[b] = fmaf(w.x, h4.x, fmaf(w.y, h4.y, fmaf(w.z, h4.z, fmaf(w.w, h4.w, acc[b]))));
                }
            }
#pragma unroll
            for (int off = 16; off; off >>= 1)
#pragma unroll
                for (int b = 0; b < 4; ++b)
                    acc[b] += __shfl_xor_sync(0xffffffffu, acc[b], off);
            if (lane < 4) {
                int b  = lane;
                int gb = bg0 + b;
                float a = (b == 0) ? acc[0] : (b == 1) ? acc[1] : (b == 2) ? acc[2] : acc[3];
                float logit = a + __ldg(&b_out[v]);
                out_logits[((size_t)gb * Tt + t) * Vv + v] = logit;
                // partitionable threefry random_bits(key_t, 32, (16,256)):
                // counter = linear index m (hi=0, lo=m), bits = w0 ^ w1
                unsigned m = (unsigned)(gb * Vv + v);
                unsigned r0, r1;
                tf2x32(kt0, kt1, 0u, m, r0, r1);
                unsigned bits = r0 ^ r1;
                float f = __uint_as_float((bits >> 9) | 0x3f800000u) - 1.0f;
                float u01 = fmaxf(f, 1.17549435e-38f);          // uniform(tiny, 1)
                float gum = -logf(-logf(u01));                  // gumbel
                __stcg(&g_val[gb * Vv + v], logit + gum);
            }
        }
        group_barrier(cnt, base + (++bar) * GB);
    }

    // ===== epilogue: last sample + h_final for this group's batches =====
    if (gbid == 0 && wid < BPG) {
        int b = bg0 + wid;
        int besti = warp_argmax_b(b, lane);
        if (lane == 0) out_samples[b * Tt + (Tt - 1)] = (float)besti;
    }
    // after t=1999 (odd), h_new lives in g_h[0]
    for (int i = gbid * NT + tid; i < BPG * Gg; i += GB * NT)
        out_hfinal[bg0 * Gg + i] = __ldcg(&g_h[0][bg0 * Gg + i]);
}

extern "C" void kernel_launch(void* const* d_in, const int* in_sizes, int n_in,
                              void* d_out, int out_size) {
    const float* cond  = (const float*)d_in[0];
    const float* h0    = (const float*)d_in[1];
    const float* W_ih  = (const float*)d_in[2];
    const float* W_hh  = (const float*)d_in[3];
    const float* b_ih  = (const float*)d_in[4];
    const float* b_hh  = (const float*)d_in[5];
    const float* W_hid = (const float*)d_in[6];
    const float* b_hid = (const float*)d_in[7];
    const float* W_out = (const float*)d_in[8];
    const float* b_out = (const float*)d_in[9];
    const float* emb   = (const float*)d_in[10];
    float* out = (float*)d_out;

    wavernn_persistent<<<NB, NT>>>(cond, h0, W_ih, W_hh, b_ih, b_hh,
                                   W_hid, b_hid, W_out, b_out, emb, out);
}

// round 16
// speedup vs baseline: 1.3509x; 1.3509x over previous
#include <cuda_runtime.h>
#include <cstdint>

// Problem sizes
#define NB   128
#define NT   256
#define Bb   16
#define Tt   2000
#define Cc   128
#define Gg   512
#define Hh   512
#define Vv   256

// Group decomposition: 4 independent groups x 32 blocks; each group owns 4 batches.
#define NG   4
#define GB   32                     // blocks per group
#define BPG  4                      // batches per group

#define NBAR 6001ULL                // barriers per launch per group: 1 init + 3*Tt
#define LAUNCH_ARR (NBAR * (unsigned long long)GB)

// ---------------- global scratch (no allocations allowed) ----------------
__device__ __align__(16) float g_h[2][Bb * Gg];    // double-buffered hidden state
__device__ __align__(16) float g_hid[Bb * Hh];
__device__ __align__(16) float g_val[Bb * Vv];     // logits + gumbel (for argmax)

// per-group monotonic arrival counters, each alone on a 512B-strided line.
__device__ __align__(1024) unsigned long long g_cnt[NG * 64];   // use [g*64]

struct __align__(16) Smem {
    float sh[BPG * Gg];    // 8KB: h staged (pre-loop + each P2); persists into P1
    float shid[BPG * Hh];  // 8KB: hid staged in P3
    float sx[BPG * Cc];    // 2KB: x = cond_t + embedding[prev]
    int   sprev[BPG];
    unsigned long long base0;
};

// ---------------- threefry2x32 (exact JAX semantics) ----------------
__device__ __forceinline__ unsigned rotl32(unsigned x, int r) {
    return (x << r) | (x >> (32 - r));
}

__device__ __forceinline__ void tf2x32(unsigned k0, unsigned k1,
                                       unsigned x0, unsigned x1,
                                       unsigned& o0, unsigned& o1) {
    unsigned ks2 = k0 ^ k1 ^ 0x1BD11BDAu;
    x0 += k0; x1 += k1;
    x0 += x1; x1 = rotl32(x1, 13); x1 ^= x0;
    x0 += x1; x1 = rotl32(x1, 15); x1 ^= x0;
    x0 += x1; x1 = rotl32(x1, 26); x1 ^= x0;
    x0 += x1; x1 = rotl32(x1, 6);  x1 ^= x0;
    x0 += k1; x1 += ks2 + 1u;
    x0 += x1; x1 = rotl32(x1, 17); x1 ^= x0;
    x0 += x1; x1 = rotl32(x1, 29); x1 ^= x0;
    x0 += x1; x1 = rotl32(x1, 16); x1 ^= x0;
    x0 += x1; x1 = rotl32(x1, 24); x1 ^= x0;
    x0 += ks2; x1 += k0 + 2u;
    x0 += x1; x1 = rotl32(x1, 13); x1 ^= x0;
    x0 += x1; x1 = rotl32(x1, 15); x1 ^= x0;
    x0 += x1; x1 = rotl32(x1, 26); x1 ^= x0;
    x0 += x1; x1 = rotl32(x1, 6);  x1 ^= x0;
    x0 += k0; x1 += k1 + 3u;
    x0 += x1; x1 = rotl32(x1, 17); x1 ^= x0;
    x0 += x1; x1 = rotl32(x1, 29); x1 ^= x0;
    x0 += x1; x1 = rotl32(x1, 16); x1 ^= x0;
    x0 += x1; x1 = rotl32(x1, 24); x1 ^= x0;
    x0 += k1; x1 += ks2 + 4u;
    x0 += x1; x1 = rotl32(x1, 13); x1 ^= x0;
    x0 += x1; x1 = rotl32(x1, 15); x1 ^= x0;
    x0 += x1; x1 = rotl32(x1, 26); x1 ^= x0;
    x0 += x1; x1 = rotl32(x1, 6);  x1 ^= x0;
    x0 += ks2; x1 += k0 + 5u;
    o0 = x0; o1 = x1;
}

__device__ __forceinline__ float sigmoidf_(float x) {
    return 1.0f / (1.0f + expf(-x));
}

// ---------------- per-group barrier: R13-exact (red.release + always-poll) -----
__device__ __forceinline__ unsigned long long cnt_acquire(const unsigned long long* p) {
    unsigned long long v;
    asm volatile("ld.acquire.gpu.global.u64 %0, [%1];" : "=l"(v) : "l"(p));
    return v;
}

__device__ __forceinline__ void group_barrier(unsigned long long* cnt,
                                              unsigned long long thresh) {
    __threadfence();      // cumulative publication of this block's global writes
    __syncthreads();
    if (threadIdx.x == 0) {
        asm volatile("red.release.gpu.global.add.u64 [%0], %1;"
                     :: "l"(cnt), "l"(1ULL) : "memory");
        while (cnt_acquire(cnt) < thresh) { }
    }
    __syncthreads();
}

// warp-cooperative argmax over g_val[b][0..255], first-index tie-break (jnp.argmax)
__device__ __forceinline__ int warp_argmax_b(int b, int lane) {
    float bestv = -1e30f; int besti = 0;
#pragma unroll
    for (int k = 0; k < 8; ++k) {
        int v = lane + 32 * k;
        float x = __ldcg(&g_val[b * Vv + v]);
        if (x > bestv) { bestv = x; besti = v; }
    }
#pragma unroll
    for (int off = 16; off; off >>= 1) {
        float ov = __shfl_xor_sync(0xffffffffu, bestv, off);
        int   oi = __shfl_xor_sync(0xffffffffu, besti, off);
        if (ov > bestv || (ov == bestv && oi < besti)) { bestv = ov; besti = oi; }
    }
    return besti;
}

// runtime select from a [2][4] register array
__device__ __forceinline__ float sel24(const float a[2][4], int uu, int b) {
    float x0 = (b == 0) ? a[0][0] : (b == 1) ? a[0][1] : (b == 2) ? a[0][2] : a[0][3];
    float x1 = (b == 0) ? a[1][0] : (b == 1) ? a[1][1] : (b == 2) ? a[1][2] : a[1][3];
    return (uu == 0) ? x0 : x1;
}

__global__ void __launch_bounds__(NT, 1)
wavernn_persistent(const float* __restrict__ cond,
                   const float* __restrict__ h0,
                   const float* __restrict__ W_ih,
                   const float* __restrict__ W_hh,
                   const float* __restrict__ b_ih,
                   const float* __restrict__ b_hh,
                   const float* __restrict__ W_hid,
                   const float* __restrict__ b_hid,
                   const float* __restrict__ W_out,
                   const float* __restrict__ b_out,
                   const float* __restrict__ emb,
                   float* __restrict__ out) {
    __shared__ Smem sm;
    const int tid  = threadIdx.x;
    const int g    = blockIdx.x >> 5;        // group id 0..3
    const int gbid = blockIdx.x & 31;        // block id within group
    const int wid  = tid >> 5;               // 8 warps
    const int lane = tid & 31;
    const int bg0  = g * BPG;                // first global batch of this group
    unsigned long long* cnt = &g_cnt[g * 64];

    if (tid == 0) {
        unsigned long long c0 = cnt_acquire(cnt);
        sm.base0 = (c0 / LAUNCH_ARR) * LAUNCH_ARR;
    }
    __syncthreads();
    const unsigned long long base = sm.base0;
    unsigned long long bar = 0;

    float* out_logits  = out;                                // [B][T][V]
    float* out_samples = out + (size_t)Bb * Tt * Vv;         // [B][T]
    float* out_hfinal  = out + (size_t)Bb * Tt * Vv + (size_t)Bb * Tt; // [B][G]

    // ---- init: h[0] = h0 for this group's batches ----
    for (int i = gbid * NT + tid; i < BPG * Gg; i += GB * NT)
        __stcg(&g_h[0][bg0 * Gg + i], h0[bg0 * Gg + i]);
    group_barrier(cnt, base + (++bar) * GB);

    // pre-stage h(0) into smem (persists across the loop; refreshed in each P2)
    {
        const float4* src = (const float4*)(g_h[0] + bg0 * Gg);
        float4* dst = (float4*)sm.sh;
        for (int i = tid; i < (BPG * Gg) / 4; i += NT) dst[i] = __ldcg(src + i);
    }
    __syncthreads();

    for (int t = 0; t < Tt; ++t) {
        const int pb = t & 1;           // g_h[pb] = current h, g_h[pb^1] = h_new

        // ===== P1 prologue: prev (argmax of last step) + stage x =====
        // (h(t-1) already resident in sm.sh from last step's P2 staging)
        if (t == 0) {
            if (tid < BPG) sm.sprev[tid] = Vv / 2;   // mid-bucket
        } else if (wid < BPG) {
            int b = bg0 + wid;
            int besti = warp_argmax_b(b, lane);
            if (lane == 0) {
                sm.sprev[wid] = besti;
                if (gbid == 0) out_samples[b * Tt + (t - 1)] = (float)besti;
            }
        }
        __syncthreads();

        for (int i = tid; i < BPG * Cc; i += NT) {
            int lb = i >> 7, c = i & (Cc - 1);
            sm.sx[i] = __ldg(&cond[((size_t)(bg0 + lb) * Tt + t) * Cc + c]) +
                       __ldg(&emb[(size_t)sm.sprev[lb] * Cc + c]);
        }
        __syncthreads();

        // ===== P1: fused GRU gates + h update (16 units/block, warp = 2 units x 4 batches) =====
        {
            const int ub = gbid * 16 + wid * 2;   // first of this warp's 2 units
            float sr[2][4], sz[2][4], si[2][4], shn[2][4];
#pragma unroll
            for (int uu = 0; uu < 2; ++uu)
#pragma unroll
                for (int b = 0; b < 4; ++b) {
                    sr[uu][b] = 0.f; sz[uu][b] = 0.f; si[uu][b] = 0.f; shn[uu][b] = 0.f;
                }

            // x part: W_ih rows (u, G+u, 2G+u), row = 32 float4
            {
                float4 wr[2], wz[2], wn[2];
#pragma unroll
                for (int uu = 0; uu < 2; ++uu) {
                    int u = ub + uu;
                    wr[uu] = __ldg((const float4*)(W_ih + (size_t)u * Cc) + lane);
                    wz[uu] = __ldg((const float4*)(W_ih + (size_t)(Gg + u) * Cc) + lane);
                    wn[uu] = __ldg((const float4*)(W_ih + (size_t)(2 * Gg + u) * Cc) + lane);
                }
#pragma unroll
                for (int b = 0; b < 4; ++b) {
                    float4 x4 = ((const float4*)(sm.sx + b * Cc))[lane];
#pragma unroll
                    for (int uu = 0; uu < 2; ++uu) {
                        sr[uu][b] = fmaf(wr[uu].x, x4.x, fmaf(wr[uu].y, x4.y, fmaf(wr[uu].z, x4.z, fmaf(wr[uu].w, x4.w, sr[uu][b]))));
                        sz[uu][b] = fmaf(wz[uu].x, x4.x, fmaf(wz[uu].y, x4.y, fmaf(wz[uu].z, x4.z, fmaf(wz[uu].w, x4.w, sz[uu][b]))));
                        si[uu][b] = fmaf(wn[uu].x, x4.x, fmaf(wn[uu].y, x4.y, fmaf(wn[uu].z, x4.z, fmaf(wn[uu].w, x4.w, si[uu][b]))));
                    }
                }
            }
            // h part: W_hh rows (u, G+u, 2G+u), row = 128 float4
#pragma unroll
            for (int k = 0; k < 4; ++k) {
                int c4 = lane + 32 * k;
                float4 wr[2], wz[2], wn[2];
#pragma unroll
                for (int uu = 0; uu < 2; ++uu) {
                    int u = ub + uu;
                    wr[uu] = __ldg((const float4*)(W_hh + (size_t)u * Gg) + c4);
                    wz[uu] = __ldg((const float4*)(W_hh + (size_t)(Gg + u) * Gg) + c4);
                    wn[uu] = __ldg((const float4*)(W_hh + (size_t)(2 * Gg + u) * Gg) + c4);
                }
#pragma unroll
                for (int b = 0; b < 4; ++b) {
                    float4 h4 = ((const float4*)(sm.sh + b * Gg))[c4];
#pragma unroll
                    for (int uu = 0; uu < 2; ++uu) {
                        sr[uu][b]  = fmaf(wr[uu].x, h4.x, fmaf(wr[uu].y, h4.y, fmaf(wr[uu].z, h4.z, fmaf(wr[uu].w, h4.w, sr[uu][b]))));
                        sz[uu][b]  = fmaf(wz[uu].x, h4.x, fmaf(wz[uu].y, h4.y, fmaf(wz[uu].z, h4.z, fmaf(wz[uu].w, h4.w, sz[uu][b]))));
                        shn[uu][b] = fmaf(wn[uu].x, h4.x, fmaf(wn[uu].y, h4.y, fmaf(wn[uu].z, h4.z, fmaf(wn[uu].w, h4.w, shn[uu][b]))));
                    }
                }
            }
            // butterfly reduce (same per-accumulator order -> bit-identical)
#pragma unroll
            for (int off = 16; off; off >>= 1) {
#pragma unroll
                for (int uu = 0; uu < 2; ++uu)
#pragma unroll
                    for (int b = 0; b < 4; ++b) {
                        sr[uu][b]  += __shfl_xor_sync(0xffffffffu, sr[uu][b],  off);
                        sz[uu][b]  += __shfl_xor_sync(0xffffffffu, sz[uu][b],  off);
                        si[uu][b]  += __shfl_xor_sync(0xffffffffu, si[uu][b],  off);
                        shn[uu][b] += __shfl_xor_sync(0xffffffffu, shn[uu][b], off);
                    }
            }
            if (lane < 8) {
                int uu = lane >> 2, b = lane & 3;
                int u  = ub + uu;
                float vr  = sel24(sr,  uu, b);
                float vz  = sel24(sz,  uu, b);
                float vi  = sel24(si,  uu, b);
                float vhn = sel24(shn, uu, b);
                float r = sigmoidf_(vr + __ldg(&b_ih[u])      + __ldg(&b_hh[u]));
                float z = sigmoidf_(vz + __ldg(&b_ih[Gg + u]) + __ldg(&b_hh[Gg + u]));
                float n = tanhf((vi + __ldg(&b_ih[2 * Gg + u])) +
                                r * (vhn + __ldg(&b_hh[2 * Gg + u])));
                float hold = sm.sh[b * Gg + u];
                __stcg(&g_h[pb ^ 1][(bg0 + b) * Gg + u], (1.0f - z) * n + z * hold);
            }
        }
        group_barrier(cnt, base + (++bar) * GB);

        // ===== P2: stage h_new (persists to next P1), hid = relu(h_new @ W_hid.T + b) =====
        {
            const float4* src = (const float4*)(g_h[pb ^ 1] + bg0 * Gg);
            float4* dst = (float4*)sm.sh;
            for (int i = tid; i < (BPG * Gg) / 4; i += NT) dst[i] = __ldcg(src + i);
        }
        __syncthreads();
        {
            const int ub = gbid * 16 + wid * 2;
            float acc[2][4];
#pragma unroll
            for (int uu = 0; uu < 2; ++uu)
#pragma unroll
                for (int b = 0; b < 4; ++b) acc[uu][b] = 0.f;
#pragma unroll
            for (int k = 0; k < 4; ++k) {
                int c4 = lane + 32 * k;
                float4 w[2];
#pragma unroll
                for (int uu = 0; uu < 2; ++uu)
                    w[uu] = __ldg((const float4*)(W_hid + (size_t)(ub + uu) * Gg) + c4);
#pragma unroll
                for (int b = 0; b < 4; ++b) {
                    float4 h4 = ((const float4*)(sm.sh + b * Gg))[c4];
#pragma unroll
                    for (int uu = 0; uu < 2; ++uu)
                        acc[uu][b] = fmaf(w[uu].x, h4.x, fmaf(w[uu].y, h4.y, fmaf(w[uu].z, h4.z, fmaf(w[uu].w, h4.w, acc[uu][b]))));
                }
            }
#pragma unroll
            for (int off = 16; off; off >>= 1)
#pragma unroll
                for (int uu = 0; uu < 2; ++uu)
#pragma unroll
                    for (int b = 0; b < 4; ++b)
                        acc[uu][b] += __shfl_xor_sync(0xffffffffu, acc[uu][b], off);
            if (lane < 8) {
                int uu = lane >> 2, b = lane & 3;
                int u  = ub + uu;
                float v = sel24(acc, uu, b);
                __stcg(&g_hid[(bg0 + b) * Hh + u], fmaxf(v + __ldg(&b_hid[u]), 0.0f));
            }
        }
        group_barrier(cnt, base + (++bar) * GB);

        // ===== P3: logits + gumbel + val (8 rows/block, warp = 1 row x 4 batches) =====
        {
            const float4* src = (const float4*)(g_hid + bg0 * Hh);
            float4* dst = (float4*)sm.shid;
            for (int i = tid; i < (BPG * Hh) / 4; i += NT) dst[i] = __ldcg(src + i);
        }
        __syncthreads();
        {
            // per-step JAX key: split(key(1), T)[t] = threefry((0,1),(0,t))
            unsigned kt0, kt1;
            tf2x32(0u, 1u, 0u, (unsigned)t, kt0, kt1);

            const int v = gbid * 8 + wid;     // 8 logit rows per block, warp = 1 row x 4 batches
            float acc[4];
#pragma unroll
            for (int b = 0; b < 4; ++b) acc[b] = 0.f;
#pragma unroll
            for (int k = 0; k < 4; ++k) {
                int c4 = lane + 32 * k;
                float4 w = __ldg((const float4*)(W_out + (size_t)v * Hh) + c4);
#pragma unroll
                for (int b = 0; b < 4; ++b) {
                    float4 h4 = ((const float4*)(sm.shid + b * Hh))[c4];
                    acc[b] = fmaf(w.x, h4.x, fmaf(w.y, h4.y, fmaf(w.z, h4.z, fmaf(w.w, h4.w, acc[b]))));
                }
            }
#pragma unroll
            for (int off = 16; off; off >>= 1)
#pragma unroll
                for (int b = 0; b < 4; ++b)
                    acc[b] += __shfl_xor_sync(0xffffffffu, acc[b], off);
            if (lane < 4) {
                int b  = lane;
                int gb = bg0 + b;
                float a = (b == 0) ? acc[0] : (b == 1) ? acc[1] : (b == 2) ? acc[2] : acc[3];
                float logit = a + __ldg(&b_out[v]);
                out_logits[((size_t)gb * Tt + t) * Vv + v] = logit;
                // partitionable threefry random_bits(key_t, 32, (16,256)):
                // counter = linear index m (hi=0, lo=m), bits = w0 ^ w1
                unsigned m = (unsigned)(gb * Vv + v);
                unsigned r0, r1;
                tf2x32(kt0, kt1, 0u, m, r0, r1);
                unsigned bits = r0 ^ r1;
                float f = __uint_as_float((bits >> 9) | 0x3f800000u) - 1.0f;
                float u01 = fmaxf(f, 1.17549435e-38f);          // uniform(tiny, 1)
                float gum = -logf(-logf(u01));                  // gumbel
                __stcg(&g_val[gb * Vv + v], logit + gum);
            }
        }
        group_barrier(cnt, base + (++bar) * GB);
    }

    // ===== epilogue: last sample + h_final for this group's batches =====
    if (gbid == 0 && wid < BPG) {
        int b = bg0 + wid;
        int besti = warp_argmax_b(b, lane);
        if (lane == 0) out_samples[b * Tt + (Tt - 1)] = (float)besti;
    }
    // after t=1999 (odd), h_new lives in g_h[0]
    for (int i = gbid * NT + tid; i < BPG * Gg; i += GB * NT)
        out_hfinal[bg0 * Gg + i] = __ldcg(&g_h[0][bg0 * Gg + i]);
}

extern "C" void kernel_launch(void* const* d_in, const int* in_sizes, int n_in,
                              void* d_out, int out_size) {
    const float* cond  = (const float*)d_in[0];
    const float* h0    = (const float*)d_in[1];
    const float* W_ih  = (const float*)d_in[2];
    const float* W_hh  = (const float*)d_in[3];
    const float* b_ih  = (const float*)d_in[4];
    const float* b_hh  = (const float*)d_in[5];
    const float* W_hid = (const float*)d_in[6];
    const float* b_hid = (const float*)d_in[7];
    const float* W_out = (const float*)d_in[8];
    const float* b_out = (const float*)d_in[9];
    const float* emb   = (const float*)d_in[10];
    float* out = (float*)d_out;

    wavernn_persistent<<<NB, NT>>>(cond, h0, W_ih, W_hh, b_ih, b_hh,
                                   W_hid, b_hid, W_out, b_out, emb, out);
}